// round 1
// baseline (speedup 1.0000x reference)
#include <cuda_runtime.h>

#define B_      2048
#define T_      256
#define LD      32
#define WPB     8
#define THREADS 256
#define BLOCKS  128

// shared-memory float offsets
#define OFF_WXI4 0        // 1024 float4
#define OFF_WHH4 4096     // 1024 float4
#define OFF_WL1  8192     // 1024 float2
#define OFF_WL3  10240    // 640 float2
#define OFF_WL2  11520    // 640 float
#define OFF_WXIA 12160    // 96 float2
#define OFF_BXI  12352    // 32 float2
#define OFF_BL1  12416    // 32 float
#define OFF_BL2  12448    // 32 float
#define OFF_BL3  12480    // 32 float2
#define OFF_HC4  12544    // 8*32 float4
#define OFF_ZP4  13568    // 8*32 float4
#define OFF_Z1   14592    // 8*32 float2
#define OFF_Z2   15104    // 8*32 float2
#define OFF_HIN  15616    // 8*32 float2
#define SMEM_FLOATS 16128 // 64512 bytes

__device__ __forceinline__ float tanh_fast(float x) {
    float y;
    asm("tanh.approx.f32 %0, %1;" : "=f"(y) : "f"(x));
    return y;
}
__device__ __forceinline__ float sigmoid_fast(float x) {
    return fmaf(0.5f, tanh_fast(0.5f * x), 0.5f);
}

__global__ void __launch_bounds__(THREADS, 1) ppo_kernel(
    const float* __restrict__ obs,
    const float* __restrict__ h0,
    const float* __restrict__ c0,
    const float* __restrict__ W1,
    const float* __restrict__ b1,
    const float* __restrict__ W_ih,
    const float* __restrict__ W_hh,
    const float* __restrict__ b_ih,
    const float* __restrict__ b_hh,
    const float* __restrict__ W_xi,
    const float* __restrict__ b_xi,
    const float* __restrict__ Wl1,
    const float* __restrict__ bl1,
    const float* __restrict__ Wl2,
    const float* __restrict__ bl2,
    const float* __restrict__ Wl3,
    const float* __restrict__ bl3,
    float* __restrict__ out)
{
    extern __shared__ float sm[];
    const int tid = threadIdx.x;
    const int wp  = tid >> 5;
    const int l   = tid & 31;
    const int gw  = blockIdx.x * WPB + wp;   // 0..1023
    const int e0  = gw * 2;
    const int e1  = e0 + 1;

    float4* s_Wxi4 = (float4*)(sm + OFF_WXI4);
    float4* s_Whh4 = (float4*)(sm + OFF_WHH4);
    float2* s_Wl1  = (float2*)(sm + OFF_WL1);
    float2* s_Wl3  = (float2*)(sm + OFF_WL3);
    float*  s_Wl2  =          sm + OFF_WL2;
    float2* s_WxiA = (float2*)(sm + OFF_WXIA);
    float2* s_bxi  = (float2*)(sm + OFF_BXI);
    float*  s_bl1  =          sm + OFF_BL1;
    float*  s_bl2  =          sm + OFF_BL2;
    float2* s_bl3  = (float2*)(sm + OFF_BL3);
    float4* s_hc4  = (float4*)(sm + OFF_HC4) + wp * 32;
    float4* s_zp4  = (float4*)(sm + OFF_ZP4) + wp * 32;
    float2* s_z1   = (float2*)(sm + OFF_Z1)  + wp * 32;
    float2* s_z2   = (float2*)(sm + OFF_Z2)  + wp * 32;
    float2* s_hin  = (float2*)(sm + OFF_HIN) + wp * 32;

    // ---- stage weights into shared (interleaved, lane-indexed layouts) ----
    for (int idx = tid; idx < 1024; idx += THREADS) {
        int k = idx >> 5, j = idx & 31;
        s_Wxi4[idx] = make_float4(W_xi[j*67 + k],      W_xi[(j+32)*67 + k],
                                  W_xi[j*67 + 32 + k], W_xi[(j+32)*67 + 32 + k]);
        s_Whh4[idx] = make_float4(W_hh[j*32 + k],      W_hh[(j+32)*32 + k],
                                  W_hh[(j+64)*32 + k], W_hh[(j+96)*32 + k]);
        float wa = (j < 20) ? Wl1[j*64 + k]      : 0.f;
        float wb = (j < 20) ? Wl1[j*64 + 32 + k] : 0.f;
        s_Wl1[idx] = make_float2(wa, wb);
    }
    for (int idx = tid; idx < 640; idx += THREADS) {
        int k = idx >> 5, j = idx & 31;   // k in 0..19
        s_Wl3[idx] = make_float2(Wl3[j*20 + k], Wl3[(j+32)*20 + k]);
        s_Wl2[idx] = (j < 20) ? Wl2[j*20 + k] : 0.f;
    }
    if (tid < 96) {
        int a = tid >> 5, j = tid & 31;
        s_WxiA[tid] = make_float2(W_xi[j*67 + 64 + a], W_xi[(j+32)*67 + 64 + a]);
    }
    if (tid < 32) {
        s_bxi[tid] = make_float2(b_xi[tid], b_xi[tid + 32]);
        s_bl1[tid] = (tid < 20) ? bl1[tid] : 0.f;
        s_bl2[tid] = (tid < 20) ? bl2[tid] : 0.f;
        s_bl3[tid] = make_float2(bl3[tid], bl3[tid + 32]);
    }

    // ---- per-lane collapsed x-path weights: W_comb = W_ih @ W1, b_comb ----
    float Wc00,Wc01,Wc02,Wc03, Wc10,Wc11,Wc12,Wc13;
    float Wc20,Wc21,Wc22,Wc23, Wc30,Wc31,Wc32,Wc33;
    float bc0, bc1, bc2, bc3;
    {
        float a0,a1,a2,a3,ab;
        #pragma unroll
        for (int g = 0; g < 4; g++) {
            int row = g*32 + l;
            a0 = a1 = a2 = a3 = ab = 0.f;
            for (int m = 0; m < 64; m++) {
                float w = W_ih[row*64 + m];
                a0 += w * W1[m*4 + 0];
                a1 += w * W1[m*4 + 1];
                a2 += w * W1[m*4 + 2];
                a3 += w * W1[m*4 + 3];
                ab += w * b1[m];
            }
            float bb = ab + b_ih[row] + b_hh[row];
            if (g == 0) { Wc00=a0; Wc01=a1; Wc02=a2; Wc03=a3; bc0=bb; }
            if (g == 1) { Wc10=a0; Wc11=a1; Wc12=a2; Wc13=a3; bc1=bb; }
            if (g == 2) { Wc20=a0; Wc21=a1; Wc22=a2; Wc23=a3; bc2=bb; }
            if (g == 3) { Wc30=a0; Wc31=a1; Wc32=a2; Wc33=a3; bc3=bb; }
        }
    }

    // ---- init recurrent state ----
    float h0r = h0[e0*LD + l], h1r = h0[e1*LD + l];
    float c0r = c0[e0*LD + l], c1r = c0[e1*LD + l];
    s_hc4[l] = make_float4(h0r, h1r, c0r, c1r);
    __syncthreads();

    const float* po0 = obs + (size_t)e0 * T_ * 7;
    const float* po1 = obs + (size_t)e1 * T_ * 7;
    float* pout0 = out + (size_t)e0 * T_ * LD + l;
    float* pout1 = out + (size_t)e1 * T_ * LD + l;
    const unsigned F = 0xffffffffu;

    for (int t = 0; t < T_; t++) {
        // load obs rows for both elements: lanes 0-6 -> e0, lanes 16-22 -> e1
        float v = 0.f;
        if (l < 7)                       v = po0[l];
        else if ((unsigned)(l-16) < 7u)  v = po1[l - 16];
        float ob00=__shfl_sync(F,v,0),  ob01=__shfl_sync(F,v,1);
        float ob02=__shfl_sync(F,v,2),  ob03=__shfl_sync(F,v,3);
        float ts00=__shfl_sync(F,v,4),  ts01=__shfl_sync(F,v,5),  a0f=__shfl_sync(F,v,6);
        float ob10=__shfl_sync(F,v,16), ob11=__shfl_sync(F,v,17);
        float ob12=__shfl_sync(F,v,18), ob13=__shfl_sync(F,v,19);
        float ts10=__shfl_sync(F,v,20), ts11=__shfl_sync(F,v,21), a1f=__shfl_sync(F,v,22);
        po0 += 7; po1 += 7;

        bool cond0 = (ts00 + ts01) != 0.f;
        bool cond1 = (ts10 + ts11) != 0.f;

        // x-path gate pre-activations (weights in registers)
        float gi0 = bc0 + Wc00*ob00 + Wc01*ob01 + Wc02*ob02 + Wc03*ob03;
        float gf0 = bc1 + Wc10*ob00 + Wc11*ob01 + Wc12*ob02 + Wc13*ob03;
        float gg0 = bc2 + Wc20*ob00 + Wc21*ob01 + Wc22*ob02 + Wc23*ob03;
        float go0 = bc3 + Wc30*ob00 + Wc31*ob01 + Wc32*ob02 + Wc33*ob03;
        float gi1 = bc0 + Wc00*ob10 + Wc01*ob11 + Wc02*ob12 + Wc03*ob13;
        float gf1 = bc1 + Wc10*ob10 + Wc11*ob11 + Wc12*ob12 + Wc13*ob13;
        float gg1 = bc2 + Wc20*ob10 + Wc21*ob11 + Wc22*ob12 + Wc23*ob13;
        float go1 = bc3 + Wc30*ob10 + Wc31*ob11 + Wc32*ob12 + Wc33*ob13;

        float hin0 = h0r, hin1 = h1r, cin0 = c0r, cin1 = c1r;

        if (cond0 || cond1) {   // warp-uniform branch
            int a0 = (int)a0f, a1 = (int)a1f;
            float2 bx = s_bxi[l];
            float2 A0 = s_WxiA[a0*32 + l];
            float2 A1 = s_WxiA[a1*32 + l];
            float zl0 = bx.x + A0.x, zh0 = bx.y + A0.y;
            float zl1 = bx.x + A1.x, zh1 = bx.y + A1.y;
            #pragma unroll
            for (int k = 0; k < 32; k++) {
                float4 hc = s_hc4[k];
                float4 w  = s_Wxi4[k*32 + l];
                zl0 += hc.x*w.x; zl1 += hc.y*w.x;
                zh0 += hc.x*w.y; zh1 += hc.y*w.y;
                zl0 += hc.z*w.z; zl1 += hc.w*w.z;
                zh0 += hc.z*w.w; zh1 += hc.w*w.w;
            }
            s_zp4[l] = make_float4(zl0, zl1, zh0, zh1);
            __syncwarp();

            float bb = s_bl1[l];
            float z10 = bb, z11 = bb;
            #pragma unroll
            for (int k = 0; k < 32; k++) {
                float4 zp = s_zp4[k];
                float2 w  = s_Wl1[k*32 + l];
                z10 += zp.x*w.x; z11 += zp.y*w.x;
                z10 += zp.z*w.y; z11 += zp.w*w.y;
            }
            z10 = fmaxf(z10, 0.f); z11 = fmaxf(z11, 0.f);
            s_z1[l] = make_float2(z10, z11);
            __syncwarp();

            float b2 = s_bl2[l];
            float z20 = b2, z21 = b2;
            #pragma unroll
            for (int k = 0; k < 20; k++) {
                float2 zv = s_z1[k];
                float w   = s_Wl2[k*32 + l];
                z20 += zv.x*w; z21 += zv.y*w;
            }
            z20 = fmaxf(z20, 0.f); z21 = fmaxf(z21, 0.f);
            s_z2[l] = make_float2(z20, z21);
            __syncwarp();

            float2 b3 = s_bl3[l];
            float dl0 = b3.x, dh0 = b3.y, dl1 = b3.x, dh1 = b3.y;
            #pragma unroll
            for (int k = 0; k < 20; k++) {
                float2 zv = s_z2[k];
                float2 w  = s_Wl3[k*32 + l];
                dl0 += zv.x*w.x; dl1 += zv.y*w.x;
                dh0 += zv.x*w.y; dh1 += zv.y*w.y;
            }
            float dt0 = ts01 - ts00, dt1 = ts11 - ts10;
            if (cond0) { hin0 = fmaf(dt0, dl0, zl0); cin0 = fmaf(dt0, dh0, zh0); }
            if (cond1) { hin1 = fmaf(dt1, dl1, zl1); cin1 = fmaf(dt1, dh1, zh1); }
        }

        s_hin[l] = make_float2(hin0, hin1);
        __syncwarp();

        // recurrent gates: += h_in @ W_hh^T
        #pragma unroll
        for (int k = 0; k < 32; k++) {
            float2 hv = s_hin[k];
            float4 w  = s_Whh4[k*32 + l];
            gi0 += hv.x*w.x; gf0 += hv.x*w.y; gg0 += hv.x*w.z; go0 += hv.x*w.w;
            gi1 += hv.y*w.x; gf1 += hv.y*w.y; gg1 += hv.y*w.z; go1 += hv.y*w.w;
        }

        // pointwise LSTM cell
        float cn0 = sigmoid_fast(gf0)*cin0 + sigmoid_fast(gi0)*tanh_fast(gg0);
        float hn0 = sigmoid_fast(go0)*tanh_fast(cn0);
        float cn1 = sigmoid_fast(gf1)*cin1 + sigmoid_fast(gi1)*tanh_fast(gg1);
        float hn1 = sigmoid_fast(go1)*tanh_fast(cn1);

        pout0[t*LD] = hn0;
        pout1[t*LD] = hn1;

        h0r = hn0; h1r = hn1; c0r = cn0; c1r = cn1;
        __syncwarp();                       // all lanes done reading s_hin/s_hc4
        s_hc4[l] = make_float4(h0r, h1r, c0r, c1r);
        __syncwarp();
    }
}

extern "C" void kernel_launch(void* const* d_in, const int* in_sizes, int n_in,
                              void* d_out, int out_size) {
    (void)in_sizes; (void)n_in; (void)out_size;
    cudaFuncSetAttribute(ppo_kernel, cudaFuncAttributeMaxDynamicSharedMemorySize,
                         SMEM_FLOATS * sizeof(float));
    ppo_kernel<<<BLOCKS, THREADS, SMEM_FLOATS * sizeof(float)>>>(
        (const float*)d_in[0],  // obs
        (const float*)d_in[1],  // h0
        (const float*)d_in[2],  // c0
        (const float*)d_in[3],  // W1
        (const float*)d_in[4],  // b1
        (const float*)d_in[5],  // W_ih
        (const float*)d_in[6],  // W_hh
        (const float*)d_in[7],  // b_ih
        (const float*)d_in[8],  // b_hh
        (const float*)d_in[9],  // W_xi
        (const float*)d_in[10], // b_xi
        (const float*)d_in[11], // Wl1
        (const float*)d_in[12], // bl1
        (const float*)d_in[13], // Wl2
        (const float*)d_in[14], // bl2
        (const float*)d_in[15], // Wl3
        (const float*)d_in[16], // bl3
        (float*)d_out);
}

// round 2
// speedup vs baseline: 1.1451x; 1.1451x over previous
#include <cuda_runtime.h>

#define B_      2048
#define T_      256
#define LD      32
#define WPB     4
#define THREADS 128
#define BLOCKS  128

// shared-memory float offsets
#define OFF_WXI4 0        // 1024 float4
#define OFF_WHH4 4096     // 1024 float4
#define OFF_WL1  8192     // 1024 float2
#define OFF_WL3  10240    // 640 float2
#define OFF_WL2  11520    // 640 float
#define OFF_WXIA 12160    // 96 float2
#define OFF_BXI  12352    // 32 float2
#define OFF_BL1  12416    // 32 float
#define OFF_BL2  12448    // 32 float
#define OFF_BL3  12480    // 32 float2
#define OFF_STAGE 12544   // 4 warps * 896 floats
#define SMEM_FLOATS 16128 // 64512 bytes

// per-warp staging sub-offsets (floats, within 896-float warp slab)
#define ST_HCH 0     // 32 float4  (h of 4 elems)
#define ST_HCC 128   // 32 float4  (c of 4 elems)
#define ST_ZPL 256   // 32 float4  (zp low half, 4 elems)
#define ST_ZPH 384   // 32 float4  (zp high half, 4 elems)
#define ST_Z1  512   // 32 float4
#define ST_Z2  640   // 32 float4
#define ST_HIN 768   // 32 float4

__device__ __forceinline__ float tanh_fast(float x) {
    float y;
    asm("tanh.approx.f32 %0, %1;" : "=f"(y) : "f"(x));
    return y;
}
__device__ __forceinline__ float sigmoid_fast(float x) {
    return fmaf(0.5f, tanh_fast(0.5f * x), 0.5f);
}

__global__ void __launch_bounds__(THREADS, 1) ppo_kernel(
    const float* __restrict__ obs,
    const float* __restrict__ h0,
    const float* __restrict__ c0,
    const float* __restrict__ W1,
    const float* __restrict__ b1,
    const float* __restrict__ W_ih,
    const float* __restrict__ W_hh,
    const float* __restrict__ b_ih,
    const float* __restrict__ b_hh,
    const float* __restrict__ W_xi,
    const float* __restrict__ b_xi,
    const float* __restrict__ Wl1,
    const float* __restrict__ bl1,
    const float* __restrict__ Wl2,
    const float* __restrict__ bl2,
    const float* __restrict__ Wl3,
    const float* __restrict__ bl3,
    float* __restrict__ out)
{
    extern __shared__ float sm[];
    const int tid = threadIdx.x;
    const int wp  = tid >> 5;
    const int l   = tid & 31;
    const int gw  = blockIdx.x * WPB + wp;   // 0..511
    const int e0  = gw * 4;

    float4* s_Wxi4 = (float4*)(sm + OFF_WXI4);
    float4* s_Whh4 = (float4*)(sm + OFF_WHH4);
    float2* s_Wl1  = (float2*)(sm + OFF_WL1);
    float2* s_Wl3  = (float2*)(sm + OFF_WL3);
    float*  s_Wl2  =          sm + OFF_WL2;
    float2* s_WxiA = (float2*)(sm + OFF_WXIA);
    float2* s_bxi  = (float2*)(sm + OFF_BXI);
    float*  s_bl1  =          sm + OFF_BL1;
    float*  s_bl2  =          sm + OFF_BL2;
    float2* s_bl3  = (float2*)(sm + OFF_BL3);

    float* slab = sm + OFF_STAGE + wp * 896;
    float4* s_hcH = (float4*)(slab + ST_HCH);
    float4* s_hcC = (float4*)(slab + ST_HCC);
    float4* s_zpL = (float4*)(slab + ST_ZPL);
    float4* s_zpH = (float4*)(slab + ST_ZPH);
    float4* s_z1  = (float4*)(slab + ST_Z1);
    float4* s_z2  = (float4*)(slab + ST_Z2);
    float4* s_hin = (float4*)(slab + ST_HIN);

    // ---- stage weights into shared (interleaved, lane-indexed layouts) ----
    for (int idx = tid; idx < 1024; idx += THREADS) {
        int k = idx >> 5, j = idx & 31;
        s_Wxi4[idx] = make_float4(W_xi[j*67 + k],      W_xi[(j+32)*67 + k],
                                  W_xi[j*67 + 32 + k], W_xi[(j+32)*67 + 32 + k]);
        s_Whh4[idx] = make_float4(W_hh[j*32 + k],      W_hh[(j+32)*32 + k],
                                  W_hh[(j+64)*32 + k], W_hh[(j+96)*32 + k]);
        float wa = (j < 20) ? Wl1[j*64 + k]      : 0.f;
        float wb = (j < 20) ? Wl1[j*64 + 32 + k] : 0.f;
        s_Wl1[idx] = make_float2(wa, wb);
    }
    for (int idx = tid; idx < 640; idx += THREADS) {
        int k = idx >> 5, j = idx & 31;   // k in 0..19
        s_Wl3[idx] = make_float2(Wl3[j*20 + k], Wl3[(j+32)*20 + k]);
        s_Wl2[idx] = (j < 20) ? Wl2[j*20 + k] : 0.f;
    }
    if (tid < 96) {
        int a = tid >> 5, j = tid & 31;
        s_WxiA[tid] = make_float2(W_xi[j*67 + 64 + a], W_xi[(j+32)*67 + 64 + a]);
    }
    if (tid < 32) {
        s_bxi[tid] = make_float2(b_xi[tid], b_xi[tid + 32]);
        s_bl1[tid] = (tid < 20) ? bl1[tid] : 0.f;
        s_bl2[tid] = (tid < 20) ? bl2[tid] : 0.f;
        s_bl3[tid] = make_float2(bl3[tid], bl3[tid + 32]);
    }

    // ---- per-lane collapsed x-path weights: W_comb = W_ih @ W1, b_comb ----
    float Wc00,Wc01,Wc02,Wc03, Wc10,Wc11,Wc12,Wc13;
    float Wc20,Wc21,Wc22,Wc23, Wc30,Wc31,Wc32,Wc33;
    float bc0, bc1, bc2, bc3;
    {
        float a0,a1,a2,a3,ab;
        #pragma unroll
        for (int g = 0; g < 4; g++) {
            int row = g*32 + l;
            a0 = a1 = a2 = a3 = ab = 0.f;
            for (int m = 0; m < 64; m++) {
                float w = W_ih[row*64 + m];
                a0 += w * W1[m*4 + 0];
                a1 += w * W1[m*4 + 1];
                a2 += w * W1[m*4 + 2];
                a3 += w * W1[m*4 + 3];
                ab += w * b1[m];
            }
            float bb = ab + b_ih[row] + b_hh[row];
            if (g == 0) { Wc00=a0; Wc01=a1; Wc02=a2; Wc03=a3; bc0=bb; }
            if (g == 1) { Wc10=a0; Wc11=a1; Wc12=a2; Wc13=a3; bc1=bb; }
            if (g == 2) { Wc20=a0; Wc21=a1; Wc22=a2; Wc23=a3; bc2=bb; }
            if (g == 3) { Wc30=a0; Wc31=a1; Wc32=a2; Wc33=a3; bc3=bb; }
        }
    }

    // ---- init recurrent state (4 elements per warp) ----
    float h0r = h0[(e0+0)*LD + l], h1r = h0[(e0+1)*LD + l];
    float h2r = h0[(e0+2)*LD + l], h3r = h0[(e0+3)*LD + l];
    float c0r = c0[(e0+0)*LD + l], c1r = c0[(e0+1)*LD + l];
    float c2r = c0[(e0+2)*LD + l], c3r = c0[(e0+3)*LD + l];
    s_hcH[l] = make_float4(h0r, h1r, h2r, h3r);
    s_hcC[l] = make_float4(c0r, c1r, c2r, c3r);
    __syncthreads();

    // obs loading: lane groups of 8; group g = l>>3 serves element e0+g, sub = l&7 (<7 active)
    const int grp = l >> 3;
    const int sub = l & 7;
    const bool act_lane = (sub < 7);
    const float* pobs = obs + (size_t)(e0 + grp) * T_ * 7 + sub;

    float* pout0 = out + (size_t)(e0+0) * T_ * LD + l;
    float* pout1 = out + (size_t)(e0+1) * T_ * LD + l;
    float* pout2 = out + (size_t)(e0+2) * T_ * LD + l;
    float* pout3 = out + (size_t)(e0+3) * T_ * LD + l;
    const unsigned F = 0xffffffffu;

    float v = act_lane ? pobs[0] : 0.f;     // obs for t=0

    for (int t = 0; t < T_; t++) {
        // prefetch obs for t+1 (hidden behind this step's compute)
        float vn = 0.f;
        if (act_lane && t + 1 < T_) vn = pobs[7];
        pobs += 7;

        float ob00=__shfl_sync(F,v,0),  ob01=__shfl_sync(F,v,1);
        float ob02=__shfl_sync(F,v,2),  ob03=__shfl_sync(F,v,3);
        float ts00=__shfl_sync(F,v,4),  ts01=__shfl_sync(F,v,5),  a0f=__shfl_sync(F,v,6);
        float ob10=__shfl_sync(F,v,8),  ob11=__shfl_sync(F,v,9);
        float ob12=__shfl_sync(F,v,10), ob13=__shfl_sync(F,v,11);
        float ts10=__shfl_sync(F,v,12), ts11=__shfl_sync(F,v,13), a1f=__shfl_sync(F,v,14);
        float ob20=__shfl_sync(F,v,16), ob21=__shfl_sync(F,v,17);
        float ob22=__shfl_sync(F,v,18), ob23=__shfl_sync(F,v,19);
        float ts20=__shfl_sync(F,v,20), ts21=__shfl_sync(F,v,21), a2f=__shfl_sync(F,v,22);
        float ob30=__shfl_sync(F,v,24), ob31=__shfl_sync(F,v,25);
        float ob32=__shfl_sync(F,v,26), ob33=__shfl_sync(F,v,27);
        float ts30=__shfl_sync(F,v,28), ts31=__shfl_sync(F,v,29), a3f=__shfl_sync(F,v,30);

        bool cond0 = (ts00 + ts01) != 0.f;
        bool cond1 = (ts10 + ts11) != 0.f;
        bool cond2 = (ts20 + ts21) != 0.f;
        bool cond3 = (ts30 + ts31) != 0.f;

        // x-path gate pre-activations (weights in registers)
        float gi0 = bc0 + Wc00*ob00 + Wc01*ob01 + Wc02*ob02 + Wc03*ob03;
        float gf0 = bc1 + Wc10*ob00 + Wc11*ob01 + Wc12*ob02 + Wc13*ob03;
        float gg0 = bc2 + Wc20*ob00 + Wc21*ob01 + Wc22*ob02 + Wc23*ob03;
        float go0 = bc3 + Wc30*ob00 + Wc31*ob01 + Wc32*ob02 + Wc33*ob03;
        float gi1 = bc0 + Wc00*ob10 + Wc01*ob11 + Wc02*ob12 + Wc03*ob13;
        float gf1 = bc1 + Wc10*ob10 + Wc11*ob11 + Wc12*ob12 + Wc13*ob13;
        float gg1 = bc2 + Wc20*ob10 + Wc21*ob11 + Wc22*ob12 + Wc23*ob13;
        float go1 = bc3 + Wc30*ob10 + Wc31*ob11 + Wc32*ob12 + Wc33*ob13;
        float gi2 = bc0 + Wc00*ob20 + Wc01*ob21 + Wc02*ob22 + Wc03*ob23;
        float gf2 = bc1 + Wc10*ob20 + Wc11*ob21 + Wc12*ob22 + Wc13*ob23;
        float gg2 = bc2 + Wc20*ob20 + Wc21*ob21 + Wc22*ob22 + Wc23*ob23;
        float go2 = bc3 + Wc30*ob20 + Wc31*ob21 + Wc32*ob22 + Wc33*ob23;
        float gi3 = bc0 + Wc00*ob30 + Wc01*ob31 + Wc02*ob32 + Wc03*ob33;
        float gf3 = bc1 + Wc10*ob30 + Wc11*ob31 + Wc12*ob32 + Wc13*ob33;
        float gg3 = bc2 + Wc20*ob30 + Wc21*ob31 + Wc22*ob32 + Wc23*ob33;
        float go3 = bc3 + Wc30*ob30 + Wc31*ob31 + Wc32*ob32 + Wc33*ob33;

        float hin0 = h0r, hin1 = h1r, hin2 = h2r, hin3 = h3r;
        float cin0 = c0r, cin1 = c1r, cin2 = c2r, cin3 = c3r;

        if (cond0 || cond1 || cond2 || cond3) {   // warp-uniform branch
            int a0 = (int)a0f, a1 = (int)a1f, a2 = (int)a2f, a3 = (int)a3f;
            float2 bx = s_bxi[l];
            float2 A0 = s_WxiA[a0*32 + l];
            float2 A1 = s_WxiA[a1*32 + l];
            float2 A2 = s_WxiA[a2*32 + l];
            float2 A3 = s_WxiA[a3*32 + l];
            float zl0 = bx.x + A0.x, zh0 = bx.y + A0.y;
            float zl1 = bx.x + A1.x, zh1 = bx.y + A1.y;
            float zl2 = bx.x + A2.x, zh2 = bx.y + A2.y;
            float zl3 = bx.x + A3.x, zh3 = bx.y + A3.y;
            #pragma unroll
            for (int k = 0; k < 32; k++) {
                float4 hH = s_hcH[k];
                float4 hC = s_hcC[k];
                float4 w  = s_Wxi4[k*32 + l];
                zl0 += hH.x*w.x; zl1 += hH.y*w.x; zl2 += hH.z*w.x; zl3 += hH.w*w.x;
                zh0 += hH.x*w.y; zh1 += hH.y*w.y; zh2 += hH.z*w.y; zh3 += hH.w*w.y;
                zl0 += hC.x*w.z; zl1 += hC.y*w.z; zl2 += hC.z*w.z; zl3 += hC.w*w.z;
                zh0 += hC.x*w.w; zh1 += hC.y*w.w; zh2 += hC.z*w.w; zh3 += hC.w*w.w;
            }
            s_zpL[l] = make_float4(zl0, zl1, zl2, zl3);
            s_zpH[l] = make_float4(zh0, zh1, zh2, zh3);
            __syncwarp();

            float bb = s_bl1[l];
            float z10 = bb, z11 = bb, z12 = bb, z13 = bb;
            #pragma unroll
            for (int k = 0; k < 32; k++) {
                float4 zL = s_zpL[k];
                float4 zH = s_zpH[k];
                float2 w  = s_Wl1[k*32 + l];
                z10 += zL.x*w.x; z11 += zL.y*w.x; z12 += zL.z*w.x; z13 += zL.w*w.x;
                z10 += zH.x*w.y; z11 += zH.y*w.y; z12 += zH.z*w.y; z13 += zH.w*w.y;
            }
            z10 = fmaxf(z10, 0.f); z11 = fmaxf(z11, 0.f);
            z12 = fmaxf(z12, 0.f); z13 = fmaxf(z13, 0.f);
            s_z1[l] = make_float4(z10, z11, z12, z13);
            __syncwarp();

            float b2 = s_bl2[l];
            float z20 = b2, z21 = b2, z22 = b2, z23 = b2;
            #pragma unroll
            for (int k = 0; k < 20; k++) {
                float4 zv = s_z1[k];
                float w   = s_Wl2[k*32 + l];
                z20 += zv.x*w; z21 += zv.y*w; z22 += zv.z*w; z23 += zv.w*w;
            }
            z20 = fmaxf(z20, 0.f); z21 = fmaxf(z21, 0.f);
            z22 = fmaxf(z22, 0.f); z23 = fmaxf(z23, 0.f);
            s_z2[l] = make_float4(z20, z21, z22, z23);
            __syncwarp();

            float2 b3 = s_bl3[l];
            float dl0 = b3.x, dl1 = b3.x, dl2 = b3.x, dl3 = b3.x;
            float dh0 = b3.y, dh1 = b3.y, dh2 = b3.y, dh3 = b3.y;
            #pragma unroll
            for (int k = 0; k < 20; k++) {
                float4 zv = s_z2[k];
                float2 w  = s_Wl3[k*32 + l];
                dl0 += zv.x*w.x; dl1 += zv.y*w.x; dl2 += zv.z*w.x; dl3 += zv.w*w.x;
                dh0 += zv.x*w.y; dh1 += zv.y*w.y; dh2 += zv.z*w.y; dh3 += zv.w*w.y;
            }
            float dt0 = ts01 - ts00, dt1 = ts11 - ts10;
            float dt2 = ts21 - ts20, dt3 = ts31 - ts30;
            if (cond0) { hin0 = fmaf(dt0, dl0, zl0); cin0 = fmaf(dt0, dh0, zh0); }
            if (cond1) { hin1 = fmaf(dt1, dl1, zl1); cin1 = fmaf(dt1, dh1, zh1); }
            if (cond2) { hin2 = fmaf(dt2, dl2, zl2); cin2 = fmaf(dt2, dh2, zh2); }
            if (cond3) { hin3 = fmaf(dt3, dl3, zl3); cin3 = fmaf(dt3, dh3, zh3); }
        }

        s_hin[l] = make_float4(hin0, hin1, hin2, hin3);
        __syncwarp();

        // recurrent gates: += h_in @ W_hh^T
        #pragma unroll
        for (int k = 0; k < 32; k++) {
            float4 hv = s_hin[k];
            float4 w  = s_Whh4[k*32 + l];
            gi0 += hv.x*w.x; gf0 += hv.x*w.y; gg0 += hv.x*w.z; go0 += hv.x*w.w;
            gi1 += hv.y*w.x; gf1 += hv.y*w.y; gg1 += hv.y*w.z; go1 += hv.y*w.w;
            gi2 += hv.z*w.x; gf2 += hv.z*w.y; gg2 += hv.z*w.z; go2 += hv.z*w.w;
            gi3 += hv.w*w.x; gf3 += hv.w*w.y; gg3 += hv.w*w.z; go3 += hv.w*w.w;
        }

        // pointwise LSTM cell
        float cn0 = sigmoid_fast(gf0)*cin0 + sigmoid_fast(gi0)*tanh_fast(gg0);
        float hn0 = sigmoid_fast(go0)*tanh_fast(cn0);
        float cn1 = sigmoid_fast(gf1)*cin1 + sigmoid_fast(gi1)*tanh_fast(gg1);
        float hn1 = sigmoid_fast(go1)*tanh_fast(cn1);
        float cn2 = sigmoid_fast(gf2)*cin2 + sigmoid_fast(gi2)*tanh_fast(gg2);
        float hn2 = sigmoid_fast(go2)*tanh_fast(cn2);
        float cn3 = sigmoid_fast(gf3)*cin3 + sigmoid_fast(gi3)*tanh_fast(gg3);
        float hn3 = sigmoid_fast(go3)*tanh_fast(cn3);

        pout0[t*LD] = hn0;
        pout1[t*LD] = hn1;
        pout2[t*LD] = hn2;
        pout3[t*LD] = hn3;

        h0r = hn0; h1r = hn1; h2r = hn2; h3r = hn3;
        c0r = cn0; c1r = cn1; c2r = cn2; c3r = cn3;
        __syncwarp();                       // all lanes done reading s_hin/s_hc
        s_hcH[l] = make_float4(h0r, h1r, h2r, h3r);
        s_hcC[l] = make_float4(c0r, c1r, c2r, c3r);
        __syncwarp();

        v = vn;
    }
}

extern "C" void kernel_launch(void* const* d_in, const int* in_sizes, int n_in,
                              void* d_out, int out_size) {
    (void)in_sizes; (void)n_in; (void)out_size;
    cudaFuncSetAttribute(ppo_kernel, cudaFuncAttributeMaxDynamicSharedMemorySize,
                         SMEM_FLOATS * sizeof(float));
    ppo_kernel<<<BLOCKS, THREADS, SMEM_FLOATS * sizeof(float)>>>(
        (const float*)d_in[0],  // obs
        (const float*)d_in[1],  // h0
        (const float*)d_in[2],  // c0
        (const float*)d_in[3],  // W1
        (const float*)d_in[4],  // b1
        (const float*)d_in[5],  // W_ih
        (const float*)d_in[6],  // W_hh
        (const float*)d_in[7],  // b_ih
        (const float*)d_in[8],  // b_hh
        (const float*)d_in[9],  // W_xi
        (const float*)d_in[10], // b_xi
        (const float*)d_in[11], // Wl1
        (const float*)d_in[12], // bl1
        (const float*)d_in[13], // Wl2
        (const float*)d_in[14], // bl2
        (const float*)d_in[15], // Wl3
        (const float*)d_in[16], // bl3
        (float*)d_out);
}